// round 1
// baseline (speedup 1.0000x reference)
#include <cuda_runtime.h>
#include <math.h>
#include <float.h>

// ---------------- problem constants ----------------
#define CB   4      // batch
#define CT   16     // temporal length
#define CS   256    // spatial length (16x16)
#define CN   4096   // tokens per batch (CT*CS)
#define CC   1152   // channels
#define CNH  16     // heads
#define CHD  72     // head dim
#define CYL  120    // cross kv length
#define NROW 16384  // CB*CN total rows

// ---------------- scratch (device globals; no allocation) ----------------
__device__ float g_t6[CB * 6 * CC];                       // modulation vectors
__device__ float g_xm[(size_t)NROW * CC];                 // LN output / generic buffer
__device__ float g_qkv[(size_t)NROW * 3 * CC];            // qkv / q buffer
__device__ float g_att[(size_t)NROW * CC];                // attention output
__device__ float g_h[(size_t)NROW * 4 * CC];              // MLP hidden
__device__ float g_sc[67108864UL];                        // scores scratch (max: spatial)
__device__ float g_kv[CB * CYL * 2 * CC];                 // cross kv

// ---------------- helpers ----------------
__device__ __forceinline__ float gelu_tanh(float x) {
    float x3 = x * x * x;
    return 0.5f * x * (1.f + tanhf(0.7978845608028654f * (x + 0.044715f * x3)));
}

// ---------------- modulation: t6 = sst + t ----------------
__global__ void k_mod(const float* __restrict__ t, const float* __restrict__ sst,
                      float* __restrict__ t6) {
    int i = blockIdx.x * blockDim.x + threadIdx.x;
    if (i < CB * 6 * CC) t6[i] = sst[i % (6 * CC)] + t[i];
}

// ---------------- LayerNorm + modulate: out = LN(x)*(1+scale)+shift ----------------
// grid = NROW blocks, block = 288 threads, 4 elements / thread
__global__ void k_ln_mod(const float* __restrict__ X, const float* __restrict__ t6,
                         float* __restrict__ out, int shiftIdx, int scaleIdx) {
    int r = blockIdx.x;
    int b = r >> 12;  // 4096 rows / batch
    const float* xr = X + (size_t)r * CC;
    const float* sh = t6 + (size_t)(b * 6 + shiftIdx) * CC;
    const float* scl = t6 + (size_t)(b * 6 + scaleIdx) * CC;

    float v[4];
    float s = 0.f, sq = 0.f;
#pragma unroll
    for (int i = 0; i < 4; i++) {
        int c = threadIdx.x + i * 288;
        v[i] = xr[c];
        s += v[i];
        sq += v[i] * v[i];
    }
    // 9-warp reduction
    __shared__ float s1[9], s2[9], bc[2];
    int lane = threadIdx.x & 31, wid = threadIdx.x >> 5;
#pragma unroll
    for (int off = 16; off > 0; off >>= 1) {
        s += __shfl_xor_sync(0xffffffffu, s, off);
        sq += __shfl_xor_sync(0xffffffffu, sq, off);
    }
    if (lane == 0) { s1[wid] = s; s2[wid] = sq; }
    __syncthreads();
    if (threadIdx.x == 0) {
        float ts = 0.f, tq = 0.f;
        for (int w = 0; w < 9; w++) { ts += s1[w]; tq += s2[w]; }
        float mean = ts * (1.f / CC);
        float var = tq * (1.f / CC) - mean * mean;
        bc[0] = mean;
        bc[1] = rsqrtf(var + 1e-6f);
    }
    __syncthreads();
    float mean = bc[0], rstd = bc[1];
    float* orow = out + (size_t)r * CC;
#pragma unroll
    for (int i = 0; i < 4; i++) {
        int c = threadIdx.x + i * 288;
        orow[c] = (v[i] - mean) * rstd * (1.f + scl[c]) + sh[c];
    }
}

// ---------------- SGEMM:  C[M,Nn] = A[M,K] @ W[Nn,K]^T + bias ----------------
// 128x128 tile, 256 threads, 8x8 per thread, K-tile 8
template <bool GELU>
__global__ __launch_bounds__(256) void k_sgemm(const float* __restrict__ A,
                                               const float* __restrict__ W,
                                               const float* __restrict__ bias,
                                               float* __restrict__ Cmat,
                                               int M, int Nn, int K) {
    __shared__ float As[8][128];
    __shared__ float Bs[8][128];
    int tid = threadIdx.x;
    int m0 = blockIdx.y * 128, n0 = blockIdx.x * 128;

    int la_m = tid >> 1;           // 0..127
    int la_k = (tid & 1) * 4;      // 0 or 4
    int ty = tid >> 4, tx = tid & 15;

    const float* Aptr = A + (size_t)(m0 + la_m) * K + la_k;
    const float* Wptr = W + (size_t)(n0 + la_m) * K + la_k;
    bool a_ok = (m0 + la_m) < M;

    float acc[8][8];
#pragma unroll
    for (int i = 0; i < 8; i++)
#pragma unroll
        for (int j = 0; j < 8; j++) acc[i][j] = 0.f;

    for (int k0 = 0; k0 < K; k0 += 8) {
        float4 av = a_ok ? *(const float4*)(Aptr + k0) : make_float4(0.f, 0.f, 0.f, 0.f);
        float4 wv = *(const float4*)(Wptr + k0);
        __syncthreads();
        As[la_k + 0][la_m] = av.x; As[la_k + 1][la_m] = av.y;
        As[la_k + 2][la_m] = av.z; As[la_k + 3][la_m] = av.w;
        Bs[la_k + 0][la_m] = wv.x; Bs[la_k + 1][la_m] = wv.y;
        Bs[la_k + 2][la_m] = wv.z; Bs[la_k + 3][la_m] = wv.w;
        __syncthreads();
#pragma unroll
        for (int kk = 0; kk < 8; kk++) {
            float a[8], b[8];
            *(float4*)(a) = *(const float4*)&As[kk][ty * 8];
            *(float4*)(a + 4) = *(const float4*)&As[kk][ty * 8 + 4];
            *(float4*)(b) = *(const float4*)&Bs[kk][tx * 8];
            *(float4*)(b + 4) = *(const float4*)&Bs[kk][tx * 8 + 4];
#pragma unroll
            for (int i = 0; i < 8; i++)
#pragma unroll
                for (int j = 0; j < 8; j++) acc[i][j] = fmaf(a[i], b[j], acc[i][j]);
        }
    }
#pragma unroll
    for (int i = 0; i < 8; i++) {
        int m = m0 + ty * 8 + i;
        if (m >= M) continue;
        float* crow = Cmat + (size_t)m * Nn;
#pragma unroll
        for (int j = 0; j < 8; j++) {
            int n = n0 + tx * 8 + j;
            float val = acc[i][j] + bias[n];
            if (GELU) val = gelu_tanh(val);
            crow[n] = val;
        }
    }
}

// ---------------- attention scores: out[z,i,j] = scale * q_i . k_j ----------------
// grid (ceil(Sk/32), ceil(Sq/32), nbatch*heads), block 256
__global__ void k_scores(const float* __restrict__ Q, const float* __restrict__ Kd,
                         float* __restrict__ out, int heads, int Sq, int Sk,
                         int qRS, int kRS, long qBS, long kBS, float scale) {
    __shared__ float qs[32][73];
    __shared__ float ks[32][73];
    int z = blockIdx.z;
    int b = z / heads, h = z - b * heads;
    const float* qb = Q + (long)b * qBS + h * CHD;
    const float* kb = Kd + (long)b * kBS + h * CHD;
    int i0 = blockIdx.y * 32, j0 = blockIdx.x * 32;
    int tid = threadIdx.x;

    for (int idx = tid; idx < 32 * CHD; idx += 256) {
        int r = idx / CHD, d = idx - r * CHD;
        int i = i0 + r;
        qs[r][d] = (i < Sq) ? qb[(long)i * qRS + d] : 0.f;
        int j = j0 + r;
        ks[r][d] = (j < Sk) ? kb[(long)j * kRS + d] : 0.f;
    }
    __syncthreads();

    int il = tid >> 3;
    int jq = (tid & 7) * 4;
    float acc[4] = {0.f, 0.f, 0.f, 0.f};
#pragma unroll 8
    for (int d = 0; d < CHD; d++) {
        float qv = qs[il][d];
#pragma unroll
        for (int jj = 0; jj < 4; jj++) acc[jj] = fmaf(qv, ks[jq + jj][d], acc[jj]);
    }
    int i = i0 + il;
    if (i < Sq) {
        float* orow = out + (long)z * Sq * Sk + (long)i * Sk;
#pragma unroll
        for (int jj = 0; jj < 4; jj++) {
            int j = j0 + jq + jj;
            if (j < Sk) orow[j] = acc[jj] * scale;
        }
    }
}

// ---------------- softmax over last dim (optional causal) ----------------
// grid = rows blocks, block = 128 (L <= 256)
__global__ void k_softmax(float* __restrict__ sc, int L, int Sq, int causal) {
    long row = blockIdx.x;
    float* p = sc + row * (long)L;
    int i = (int)(row % Sq);
    int tid = threadIdx.x;
    int j0 = tid, j1 = tid + 128;

    float a0 = -FLT_MAX, a1 = -FLT_MAX;
    if (j0 < L) { a0 = p[j0]; if (causal && j0 > i) a0 = -FLT_MAX; }
    if (j1 < L) { a1 = p[j1]; if (causal && j1 > i) a1 = -FLT_MAX; }

    __shared__ float red[4];
    float m = fmaxf(a0, a1);
#pragma unroll
    for (int off = 16; off > 0; off >>= 1) m = fmaxf(m, __shfl_xor_sync(0xffffffffu, m, off));
    if ((tid & 31) == 0) red[tid >> 5] = m;
    __syncthreads();
    m = fmaxf(fmaxf(red[0], red[1]), fmaxf(red[2], red[3]));
    __syncthreads();

    float e0 = (j0 < L) ? expf(a0 - m) : 0.f;
    float e1 = (j1 < L) ? expf(a1 - m) : 0.f;
    float s = e0 + e1;
#pragma unroll
    for (int off = 16; off > 0; off >>= 1) s += __shfl_xor_sync(0xffffffffu, s, off);
    if ((tid & 31) == 0) red[tid >> 5] = s;
    __syncthreads();
    s = red[0] + red[1] + red[2] + red[3];
    float inv = 1.f / s;
    if (j0 < L) p[j0] = e0 * inv;
    if (j1 < L) p[j1] = e1 * inv;
}

// ---------------- attn @ V : O[z,i,d] = sum_j A[z,i,j] * V[z,j,d] ----------------
// block (72, 8), grid (ceil(Sq/8), nbatch*heads)
__global__ void k_av(const float* __restrict__ Asc, const float* __restrict__ V,
                     float* __restrict__ O, int heads, int Sq, int Sk,
                     int vRS, long vBS, int oRS, long oBS) {
    __shared__ float vs[32][73];
    __shared__ float as[8][32];
    int z = blockIdx.y;
    int b = z / heads, h = z - b * heads;
    const float* Ab = Asc + (long)z * Sq * Sk;
    const float* Vb = V + (long)b * vBS + h * CHD;
    float* Ob = O + (long)b * oBS + h * CHD;

    int d = threadIdx.x, ii = threadIdx.y;
    int i = blockIdx.x * 8 + ii;
    int tid = ii * 72 + d;
    float acc = 0.f;

    for (int jt = 0; jt < Sk; jt += 32) {
        for (int idx = tid; idx < 32 * CHD; idx += 576) {
            int r = idx / CHD, dd = idx - r * CHD;
            int j = jt + r;
            vs[r][dd] = (j < Sk) ? Vb[(long)j * vRS + dd] : 0.f;
        }
        if (tid < 256) {
            int r = tid >> 5, jj = tid & 31;
            int ig = blockIdx.x * 8 + r;
            int j = jt + jj;
            as[r][jj] = (ig < Sq && j < Sk) ? Ab[(long)ig * Sk + j] : 0.f;
        }
        __syncthreads();
#pragma unroll
        for (int jj = 0; jj < 32; jj++) acc = fmaf(as[ii][jj], vs[jj][d], acc);
        __syncthreads();
    }
    if (i < Sq) Ob[(long)i * oRS + d] = acc;
}

// ---------------- build temporal input: xt[(b*S+s)*T+t] = X[b, t*S+s] + tpe[t] ----------------
__global__ void k_xt_build(const float* __restrict__ X, const float* __restrict__ tpe,
                           float* __restrict__ out) {
    int r = blockIdx.x;
    int t = r & 15;
    int bs = r >> 4;
    int s = bs & 255;
    int b = bs >> 8;
    const float* xr = X + ((size_t)b * CN + t * CS + s) * CC;
    const float* tp = tpe + (size_t)t * CC;
    float* orow = out + (size_t)r * CC;
#pragma unroll
    for (int i = 0; i < 4; i++) {
        int c = threadIdx.x + i * 288;
        orow[c] = xr[c] + tp[c];
    }
}

// ---------------- residual add: X += gate * src (gate per batch,channel; gi<0 -> 1) ----
__global__ void k_resadd(float* __restrict__ X, const float* __restrict__ src,
                         const float* __restrict__ t6, int gi) {
    int r = blockIdx.x;
    int b = r >> 12;
    float* xr = X + (size_t)r * CC;
    const float* sr = src + (size_t)r * CC;
    const float* gr = (gi >= 0) ? t6 + (size_t)(b * 6 + gi) * CC : nullptr;
#pragma unroll
    for (int i = 0; i < 4; i++) {
        int c = threadIdx.x + i * 288;
        float g = gr ? gr[c] : 1.f;
        xr[c] += g * sr[c];
    }
}

// ---------------- temporal residual scatter: X[b,t*S+s] += gate * src[(b*S+s)*T+t] ----
__global__ void k_resadd_t(float* __restrict__ X, const float* __restrict__ src,
                           const float* __restrict__ t6, int gi) {
    int r = blockIdx.x;         // row in X order
    int b = r >> 12;
    int n = r & 4095;
    int t = n >> 8;
    int s = n & 255;
    long srow = ((long)(b * CS + s) * CT + t) * CC;
    float* xr = X + (size_t)r * CC;
    const float* sr = src + srow;
    const float* gr = t6 + (size_t)(b * 6 + gi) * CC;
#pragma unroll
    for (int i = 0; i < 4; i++) {
        int c = threadIdx.x + i * 288;
        xr[c] += gr[c] * sr[c];
    }
}

// =======================================================================
extern "C" void kernel_launch(void* const* d_in, const int* in_sizes, int n_in,
                              void* d_out, int out_size) {
    const float* x      = (const float*)d_in[0];
    const float* y      = (const float*)d_in[1];
    const float* t      = (const float*)d_in[2];
    const float* tpe    = (const float*)d_in[3];
    const float* sst    = (const float*)d_in[4];
    const float* qkv_s_w = (const float*)d_in[5];
    const float* qkv_s_b = (const float*)d_in[6];
    const float* proj_s_w = (const float*)d_in[7];
    const float* proj_s_b = (const float*)d_in[8];
    const float* qkv_t_w = (const float*)d_in[9];
    const float* qkv_t_b = (const float*)d_in[10];
    const float* proj_t_w = (const float*)d_in[11];
    const float* proj_t_b = (const float*)d_in[12];
    const float* q_c_w  = (const float*)d_in[13];
    const float* q_c_b  = (const float*)d_in[14];
    const float* kv_c_w = (const float*)d_in[15];
    const float* kv_c_b = (const float*)d_in[16];
    const float* proj_c_w = (const float*)d_in[17];
    const float* proj_c_b = (const float*)d_in[18];
    const float* fc1_w  = (const float*)d_in[19];
    const float* fc1_b  = (const float*)d_in[20];
    const float* fc2_w  = (const float*)d_in[21];
    const float* fc2_b  = (const float*)d_in[22];
    float* X = (float*)d_out;

    float *p_t6, *p_xm, *p_qkv, *p_att, *p_h, *p_sc, *p_kv;
    cudaGetSymbolAddress((void**)&p_t6, g_t6);
    cudaGetSymbolAddress((void**)&p_xm, g_xm);
    cudaGetSymbolAddress((void**)&p_qkv, g_qkv);
    cudaGetSymbolAddress((void**)&p_att, g_att);
    cudaGetSymbolAddress((void**)&p_h, g_h);
    cudaGetSymbolAddress((void**)&p_sc, g_sc);
    cudaGetSymbolAddress((void**)&p_kv, g_kv);

    const float scale = 0.11785113019775793f;  // 1/sqrt(72)

    // X = x (residual accumulator lives in d_out)
    cudaMemcpyAsync(X, x, (size_t)NROW * CC * sizeof(float), cudaMemcpyDeviceToDevice);

    // modulation vectors
    k_mod<<<(CB * 6 * CC + 255) / 256, 256>>>(t, sst, p_t6);

    // ---- spatial attention ----
    k_ln_mod<<<NROW, 288>>>(X, p_t6, p_xm, /*shift*/0, /*scale*/1);
    k_sgemm<false><<<dim3(3 * CC / 128, NROW / 128), 256>>>(p_xm, qkv_s_w, qkv_s_b, p_qkv,
                                                            NROW, 3 * CC, CC);
    k_scores<<<dim3(8, 8, CB * CT * CNH), 256>>>(p_qkv, p_qkv + CC, p_sc, CNH, CS, CS,
                                                 3 * CC, 3 * CC,
                                                 (long)CS * 3 * CC, (long)CS * 3 * CC, scale);
    k_softmax<<<CB * CT * CNH * CS, 128>>>(p_sc, CS, CS, 0);
    k_av<<<dim3(CS / 8, CB * CT * CNH), dim3(72, 8)>>>(p_sc, p_qkv + 2 * CC, p_att, CNH, CS, CS,
                                                       3 * CC, (long)CS * 3 * CC,
                                                       CC, (long)CS * CC);
    k_sgemm<false><<<dim3(CC / 128, NROW / 128), 256>>>(p_att, proj_s_w, proj_s_b, p_xm,
                                                        NROW, CC, CC);
    k_resadd<<<NROW, 288>>>(X, p_xm, p_t6, /*gate_msa*/2);

    // ---- temporal attention (causal) ----
    k_xt_build<<<NROW, 288>>>(X, tpe, p_xm);
    k_sgemm<false><<<dim3(3 * CC / 128, NROW / 128), 256>>>(p_xm, qkv_t_w, qkv_t_b, p_qkv,
                                                            NROW, 3 * CC, CC);
    k_scores<<<dim3(1, 1, CB * CS * CNH), 256>>>(p_qkv, p_qkv + CC, p_sc, CNH, CT, CT,
                                                 3 * CC, 3 * CC,
                                                 (long)CT * 3 * CC, (long)CT * 3 * CC, scale);
    k_softmax<<<CB * CS * CNH * CT, 128>>>(p_sc, CT, CT, 1);
    k_av<<<dim3(CT / 8, CB * CS * CNH), dim3(72, 8)>>>(p_sc, p_qkv + 2 * CC, p_att, CNH, CT, CT,
                                                       3 * CC, (long)CT * 3 * CC,
                                                       CC, (long)CT * CC);
    k_sgemm<false><<<dim3(CC / 128, NROW / 128), 256>>>(p_att, proj_t_w, proj_t_b, p_xm,
                                                        NROW, CC, CC);
    k_resadd_t<<<NROW, 288>>>(X, p_xm, p_t6, /*gate_msa*/2);

    // ---- cross attention ----
    k_sgemm<false><<<dim3(CC / 128, NROW / 128), 256>>>(X, q_c_w, q_c_b, p_qkv,
                                                        NROW, CC, CC);
    k_sgemm<false><<<dim3(2 * CC / 128, (CB * CYL + 127) / 128), 256>>>(y, kv_c_w, kv_c_b, p_kv,
                                                                        CB * CYL, 2 * CC, CC);
    k_scores<<<dim3((CYL + 31) / 32, CN / 32, CB * CNH), 256>>>(p_qkv, p_kv, p_sc, CNH, CN, CYL,
                                                                CC, 2 * CC,
                                                                (long)CN * CC, (long)CYL * 2 * CC,
                                                                scale);
    k_softmax<<<CB * CNH * CN, 128>>>(p_sc, CYL, CN, 0);
    k_av<<<dim3(CN / 8, CB * CNH), dim3(72, 8)>>>(p_sc, p_kv + CC, p_att, CNH, CN, CYL,
                                                  2 * CC, (long)CYL * 2 * CC,
                                                  CC, (long)CN * CC);
    k_sgemm<false><<<dim3(CC / 128, NROW / 128), 256>>>(p_att, proj_c_w, proj_c_b, p_xm,
                                                        NROW, CC, CC);
    k_resadd<<<NROW, 288>>>(X, p_xm, p_t6, /*no gate*/-1);

    // ---- MLP ----
    k_ln_mod<<<NROW, 288>>>(X, p_t6, p_xm, /*shift_mlp*/3, /*scale_mlp*/4);
    k_sgemm<true><<<dim3(4 * CC / 128, NROW / 128), 256>>>(p_xm, fc1_w, fc1_b, p_h,
                                                           NROW, 4 * CC, CC);
    k_sgemm<false><<<dim3(CC / 128, NROW / 128), 256>>>(p_h, fc2_w, fc2_b, p_att,
                                                        NROW, CC, 4 * CC);
    k_resadd<<<NROW, 288>>>(X, p_att, p_t6, /*gate_mlp*/5);
}

// round 2
// speedup vs baseline: 2.4513x; 2.4513x over previous
#include <cuda_runtime.h>
#include <math.h>
#include <float.h>
#include <stdint.h>

// ---------------- problem constants ----------------
#define CB   4      // batch
#define CT   16     // temporal length
#define CS   256    // spatial length (16x16)
#define CN   4096   // tokens per batch (CT*CS)
#define CC   1152   // channels
#define CNH  16     // heads
#define CHD  72     // head dim
#define CYL  120    // cross kv length
#define NROW 16384  // CB*CN total rows

// ---------------- scratch (device globals; no allocation) ----------------
__device__ float g_t6[CB * 6 * CC];                       // modulation vectors
__device__ float g_xm[(size_t)NROW * CC];                 // LN output / generic buffer
__device__ float g_qkv[(size_t)NROW * 3 * CC];            // qkv / q buffer
__device__ float g_att[(size_t)NROW * CC];                // attention output
__device__ float g_h[(size_t)NROW * 4 * CC];              // MLP hidden
__device__ float g_sc[67108864UL];                        // scores scratch (max: spatial)
__device__ float g_kv[CB * CYL * 2 * CC];                 // cross kv

// ---------------- helpers ----------------
__device__ __forceinline__ float gelu_tanh(float x) {
    float x3 = x * x * x;
    return 0.5f * x * (1.f + tanhf(0.7978845608028654f * (x + 0.044715f * x3)));
}

__device__ __forceinline__ uint32_t f2tf(float f) {
    uint32_t u;
    asm("cvt.rna.tf32.f32 %0, %1;" : "=r"(u) : "f"(f));
    return u;
}

__device__ __forceinline__ void cp_async16(void* smem, const void* gmem) {
    uint32_t s = (uint32_t)__cvta_generic_to_shared(smem);
    asm volatile("cp.async.cg.shared.global [%0], [%1], 16;\n" :: "r"(s), "l"(gmem));
}
__device__ __forceinline__ void cp_commit() { asm volatile("cp.async.commit_group;\n"); }
template <int Nk>
__device__ __forceinline__ void cp_wait() { asm volatile("cp.async.wait_group %0;\n" :: "n"(Nk)); }

// ---------------- modulation: t6 = sst + t ----------------
__global__ void k_mod(const float* __restrict__ t, const float* __restrict__ sst,
                      float* __restrict__ t6) {
    int i = blockIdx.x * blockDim.x + threadIdx.x;
    if (i < CB * 6 * CC) t6[i] = sst[i % (6 * CC)] + t[i];
}

// ---------------- LayerNorm + modulate ----------------
__global__ void k_ln_mod(const float* __restrict__ X, const float* __restrict__ t6,
                         float* __restrict__ out, int shiftIdx, int scaleIdx) {
    int r = blockIdx.x;
    int b = r >> 12;
    const float* xr = X + (size_t)r * CC;
    const float* sh = t6 + (size_t)(b * 6 + shiftIdx) * CC;
    const float* scl = t6 + (size_t)(b * 6 + scaleIdx) * CC;

    float v[4];
    float s = 0.f, sq = 0.f;
#pragma unroll
    for (int i = 0; i < 4; i++) {
        int c = threadIdx.x + i * 288;
        v[i] = xr[c];
        s += v[i];
        sq += v[i] * v[i];
    }
    __shared__ float s1[9], s2[9], bc[2];
    int lane = threadIdx.x & 31, wid = threadIdx.x >> 5;
#pragma unroll
    for (int off = 16; off > 0; off >>= 1) {
        s += __shfl_xor_sync(0xffffffffu, s, off);
        sq += __shfl_xor_sync(0xffffffffu, sq, off);
    }
    if (lane == 0) { s1[wid] = s; s2[wid] = sq; }
    __syncthreads();
    if (threadIdx.x == 0) {
        float ts = 0.f, tq = 0.f;
        for (int w = 0; w < 9; w++) { ts += s1[w]; tq += s2[w]; }
        float mean = ts * (1.f / CC);
        float var = tq * (1.f / CC) - mean * mean;
        bc[0] = mean;
        bc[1] = rsqrtf(var + 1e-6f);
    }
    __syncthreads();
    float mean = bc[0], rstd = bc[1];
    float* orow = out + (size_t)r * CC;
#pragma unroll
    for (int i = 0; i < 4; i++) {
        int c = threadIdx.x + i * 288;
        orow[c] = (v[i] - mean) * rstd * (1.f + scl[c]) + sh[c];
    }
}

// ---------------- TF32 tensor-core GEMM: C[M,N] = A[M,K] @ W[N,K]^T + bias -------
// 128x128x16 block tile, 256 threads (8 warps 2x4), warp tile 64x32 via m16n8k8.
#define TBM 128
#define TBN 128
#define TBK 16
#define ASTR 20   // smem row stride in floats (pad 4; 80B keeps 16B alignment)

template <bool GELU>
__global__ __launch_bounds__(256) void k_tgemm(const float* __restrict__ A,
                                               const float* __restrict__ W,
                                               const float* __restrict__ bias,
                                               float* __restrict__ Cmat,
                                               int M, int Nn, int K) {
    __shared__ float As[2][TBM * ASTR];
    __shared__ float Bs[2][TBN * ASTR];

    const int tid = threadIdx.x;
    const int m0 = blockIdx.y * TBM, n0 = blockIdx.x * TBN;
    const int wid = tid >> 5, lane = tid & 31;
    const int wr = wid >> 2, wc = wid & 3;          // 2 x 4 warps
    const int warp_m = wr * 64, warp_n = wc * 32;   // 64x32 warp tile
    const int qr = lane >> 2, qc = lane & 3;

    float acc[4][4][4];
#pragma unroll
    for (int mi = 0; mi < 4; mi++)
#pragma unroll
        for (int ni = 0; ni < 4; ni++)
#pragma unroll
            for (int c = 0; c < 4; c++) acc[mi][ni][c] = 0.f;

    auto load_tile = [&](int stg, int kbase) {
#pragma unroll
        for (int i = 0; i < 2; i++) {
            int ch = tid + i * 256;        // 0..511
            int m = ch >> 2;               // 0..127
            int k4 = (ch & 3) * 4;         // 0,4,8,12
            int gm = m0 + m; if (gm >= M) gm = M - 1;
            cp_async16(&As[stg][m * ASTR + k4], A + (size_t)gm * K + kbase + k4);
            cp_async16(&Bs[stg][m * ASTR + k4], W + (size_t)(n0 + m) * K + kbase + k4);
        }
    };

    const int KT = K >> 4;
    load_tile(0, 0);
    cp_commit();

    for (int kt = 0; kt < KT; ++kt) {
        int cur = kt & 1;
        if (kt + 1 < KT) {
            load_tile(1 - cur, (kt + 1) << 4);
            cp_commit();
            cp_wait<1>();
        } else {
            cp_wait<0>();
        }
        __syncthreads();

#pragma unroll
        for (int kk = 0; kk < TBK; kk += 8) {
            uint32_t af[4][4], bf[4][2];
#pragma unroll
            for (int mi = 0; mi < 4; mi++) {
                const float* base = &As[cur][(warp_m + mi * 16 + qr) * ASTR + kk + qc];
                af[mi][0] = f2tf(base[0]);
                af[mi][1] = f2tf(base[8 * ASTR]);
                af[mi][2] = f2tf(base[4]);
                af[mi][3] = f2tf(base[8 * ASTR + 4]);
            }
#pragma unroll
            for (int ni = 0; ni < 4; ni++) {
                const float* base = &Bs[cur][(warp_n + ni * 8 + qr) * ASTR + kk + qc];
                bf[ni][0] = f2tf(base[0]);
                bf[ni][1] = f2tf(base[4]);
            }
#pragma unroll
            for (int mi = 0; mi < 4; mi++)
#pragma unroll
                for (int ni = 0; ni < 4; ni++) {
                    asm volatile(
                        "mma.sync.aligned.m16n8k8.row.col.f32.tf32.tf32.f32 "
                        "{%0,%1,%2,%3}, {%4,%5,%6,%7}, {%8,%9}, {%0,%1,%2,%3};\n"
                        : "+f"(acc[mi][ni][0]), "+f"(acc[mi][ni][1]),
                          "+f"(acc[mi][ni][2]), "+f"(acc[mi][ni][3])
                        : "r"(af[mi][0]), "r"(af[mi][1]), "r"(af[mi][2]), "r"(af[mi][3]),
                          "r"(bf[ni][0]), "r"(bf[ni][1]));
                }
        }
        __syncthreads();
    }

    // epilogue
#pragma unroll
    for (int mi = 0; mi < 4; mi++) {
        int r0 = m0 + warp_m + mi * 16 + qr;
        int r1 = r0 + 8;
#pragma unroll
        for (int ni = 0; ni < 4; ni++) {
            int c0 = n0 + warp_n + ni * 8 + qc * 2;
            float b0 = bias[c0], b1 = bias[c0 + 1];
            if (r0 < M) {
                float v0 = acc[mi][ni][0] + b0;
                float v1 = acc[mi][ni][1] + b1;
                if (GELU) { v0 = gelu_tanh(v0); v1 = gelu_tanh(v1); }
                Cmat[(size_t)r0 * Nn + c0] = v0;
                Cmat[(size_t)r0 * Nn + c0 + 1] = v1;
            }
            if (r1 < M) {
                float v2 = acc[mi][ni][2] + b0;
                float v3 = acc[mi][ni][3] + b1;
                if (GELU) { v2 = gelu_tanh(v2); v3 = gelu_tanh(v3); }
                Cmat[(size_t)r1 * Nn + c0] = v2;
                Cmat[(size_t)r1 * Nn + c0 + 1] = v3;
            }
        }
    }
}

// ---------------- attention scores ----------------
__global__ void k_scores(const float* __restrict__ Q, const float* __restrict__ Kd,
                         float* __restrict__ out, int heads, int Sq, int Sk,
                         int qRS, int kRS, long qBS, long kBS, float scale) {
    __shared__ float qs[32][73];
    __shared__ float ks[32][73];
    int z = blockIdx.z;
    int b = z / heads, h = z - b * heads;
    const float* qb = Q + (long)b * qBS + h * CHD;
    const float* kb = Kd + (long)b * kBS + h * CHD;
    int i0 = blockIdx.y * 32, j0 = blockIdx.x * 32;
    int tid = threadIdx.x;

    for (int idx = tid; idx < 32 * CHD; idx += 256) {
        int r = idx / CHD, d = idx - r * CHD;
        int i = i0 + r;
        qs[r][d] = (i < Sq) ? qb[(long)i * qRS + d] : 0.f;
        int j = j0 + r;
        ks[r][d] = (j < Sk) ? kb[(long)j * kRS + d] : 0.f;
    }
    __syncthreads();

    int il = tid >> 3;
    int jq = (tid & 7) * 4;
    float acc[4] = {0.f, 0.f, 0.f, 0.f};
#pragma unroll 8
    for (int d = 0; d < CHD; d++) {
        float qv = qs[il][d];
#pragma unroll
        for (int jj = 0; jj < 4; jj++) acc[jj] = fmaf(qv, ks[jq + jj][d], acc[jj]);
    }
    int i = i0 + il;
    if (i < Sq) {
        float* orow = out + (long)z * Sq * Sk + (long)i * Sk;
#pragma unroll
        for (int jj = 0; jj < 4; jj++) {
            int j = j0 + jq + jj;
            if (j < Sk) orow[j] = acc[jj] * scale;
        }
    }
}

// ---------------- softmax ----------------
__global__ void k_softmax(float* __restrict__ sc, int L, int Sq, int causal) {
    long row = blockIdx.x;
    float* p = sc + row * (long)L;
    int i = (int)(row % Sq);
    int tid = threadIdx.x;
    int j0 = tid, j1 = tid + 128;

    float a0 = -FLT_MAX, a1 = -FLT_MAX;
    if (j0 < L) { a0 = p[j0]; if (causal && j0 > i) a0 = -FLT_MAX; }
    if (j1 < L) { a1 = p[j1]; if (causal && j1 > i) a1 = -FLT_MAX; }

    __shared__ float red[4];
    float m = fmaxf(a0, a1);
#pragma unroll
    for (int off = 16; off > 0; off >>= 1) m = fmaxf(m, __shfl_xor_sync(0xffffffffu, m, off));
    if ((tid & 31) == 0) red[tid >> 5] = m;
    __syncthreads();
    m = fmaxf(fmaxf(red[0], red[1]), fmaxf(red[2], red[3]));
    __syncthreads();

    float e0 = (j0 < L) ? expf(a0 - m) : 0.f;
    float e1 = (j1 < L) ? expf(a1 - m) : 0.f;
    float s = e0 + e1;
#pragma unroll
    for (int off = 16; off > 0; off >>= 1) s += __shfl_xor_sync(0xffffffffu, s, off);
    if ((tid & 31) == 0) red[tid >> 5] = s;
    __syncthreads();
    s = red[0] + red[1] + red[2] + red[3];
    float inv = 1.f / s;
    if (j0 < L) p[j0] = e0 * inv;
    if (j1 < L) p[j1] = e1 * inv;
}

// ---------------- attn @ V ----------------
__global__ void k_av(const float* __restrict__ Asc, const float* __restrict__ V,
                     float* __restrict__ O, int heads, int Sq, int Sk,
                     int vRS, long vBS, int oRS, long oBS) {
    __shared__ float vs[32][73];
    __shared__ float as[8][32];
    int z = blockIdx.y;
    int b = z / heads, h = z - b * heads;
    const float* Ab = Asc + (long)z * Sq * Sk;
    const float* Vb = V + (long)b * vBS + h * CHD;
    float* Ob = O + (long)b * oBS + h * CHD;

    int d = threadIdx.x, ii = threadIdx.y;
    int i = blockIdx.x * 8 + ii;
    int tid = ii * 72 + d;
    float acc = 0.f;

    for (int jt = 0; jt < Sk; jt += 32) {
        for (int idx = tid; idx < 32 * CHD; idx += 576) {
            int r = idx / CHD, dd = idx - r * CHD;
            int j = jt + r;
            vs[r][dd] = (j < Sk) ? Vb[(long)j * vRS + dd] : 0.f;
        }
        if (tid < 256) {
            int r = tid >> 5, jj = tid & 31;
            int ig = blockIdx.x * 8 + r;
            int j = jt + jj;
            as[r][jj] = (ig < Sq && j < Sk) ? Ab[(long)ig * Sk + j] : 0.f;
        }
        __syncthreads();
#pragma unroll
        for (int jj = 0; jj < 32; jj++) acc = fmaf(as[ii][jj], vs[jj][d], acc);
        __syncthreads();
    }
    if (i < Sq) Ob[(long)i * oRS + d] = acc;
}

// ---------------- build temporal input ----------------
__global__ void k_xt_build(const float* __restrict__ X, const float* __restrict__ tpe,
                           float* __restrict__ out) {
    int r = blockIdx.x;
    int t = r & 15;
    int bs = r >> 4;
    int s = bs & 255;
    int b = bs >> 8;
    const float* xr = X + ((size_t)b * CN + t * CS + s) * CC;
    const float* tp = tpe + (size_t)t * CC;
    float* orow = out + (size_t)r * CC;
#pragma unroll
    for (int i = 0; i < 4; i++) {
        int c = threadIdx.x + i * 288;
        orow[c] = xr[c] + tp[c];
    }
}

// ---------------- residual add ----------------
__global__ void k_resadd(float* __restrict__ X, const float* __restrict__ src,
                         const float* __restrict__ t6, int gi) {
    int r = blockIdx.x;
    int b = r >> 12;
    float* xr = X + (size_t)r * CC;
    const float* sr = src + (size_t)r * CC;
    const float* gr = (gi >= 0) ? t6 + (size_t)(b * 6 + gi) * CC : nullptr;
#pragma unroll
    for (int i = 0; i < 4; i++) {
        int c = threadIdx.x + i * 288;
        float g = gr ? gr[c] : 1.f;
        xr[c] += g * sr[c];
    }
}

// ---------------- temporal residual scatter ----------------
__global__ void k_resadd_t(float* __restrict__ X, const float* __restrict__ src,
                           const float* __restrict__ t6, int gi) {
    int r = blockIdx.x;
    int b = r >> 12;
    int n = r & 4095;
    int t = n >> 8;
    int s = n & 255;
    long srow = ((long)(b * CS + s) * CT + t) * CC;
    float* xr = X + (size_t)r * CC;
    const float* sr = src + srow;
    const float* gr = t6 + (size_t)(b * 6 + gi) * CC;
#pragma unroll
    for (int i = 0; i < 4; i++) {
        int c = threadIdx.x + i * 288;
        xr[c] += gr[c] * sr[c];
    }
}

// =======================================================================
extern "C" void kernel_launch(void* const* d_in, const int* in_sizes, int n_in,
                              void* d_out, int out_size) {
    const float* x      = (const float*)d_in[0];
    const float* y      = (const float*)d_in[1];
    const float* t      = (const float*)d_in[2];
    const float* tpe    = (const float*)d_in[3];
    const float* sst    = (const float*)d_in[4];
    const float* qkv_s_w = (const float*)d_in[5];
    const float* qkv_s_b = (const float*)d_in[6];
    const float* proj_s_w = (const float*)d_in[7];
    const float* proj_s_b = (const float*)d_in[8];
    const float* qkv_t_w = (const float*)d_in[9];
    const float* qkv_t_b = (const float*)d_in[10];
    const float* proj_t_w = (const float*)d_in[11];
    const float* proj_t_b = (const float*)d_in[12];
    const float* q_c_w  = (const float*)d_in[13];
    const float* q_c_b  = (const float*)d_in[14];
    const float* kv_c_w = (const float*)d_in[15];
    const float* kv_c_b = (const float*)d_in[16];
    const float* proj_c_w = (const float*)d_in[17];
    const float* proj_c_b = (const float*)d_in[18];
    const float* fc1_w  = (const float*)d_in[19];
    const float* fc1_b  = (const float*)d_in[20];
    const float* fc2_w  = (const float*)d_in[21];
    const float* fc2_b  = (const float*)d_in[22];
    float* X = (float*)d_out;

    float *p_t6, *p_xm, *p_qkv, *p_att, *p_h, *p_sc, *p_kv;
    cudaGetSymbolAddress((void**)&p_t6, g_t6);
    cudaGetSymbolAddress((void**)&p_xm, g_xm);
    cudaGetSymbolAddress((void**)&p_qkv, g_qkv);
    cudaGetSymbolAddress((void**)&p_att, g_att);
    cudaGetSymbolAddress((void**)&p_h, g_h);
    cudaGetSymbolAddress((void**)&p_sc, g_sc);
    cudaGetSymbolAddress((void**)&p_kv, g_kv);

    const float scale = 0.11785113019775793f;  // 1/sqrt(72)

    cudaMemcpyAsync(X, x, (size_t)NROW * CC * sizeof(float), cudaMemcpyDeviceToDevice);
    k_mod<<<(CB * 6 * CC + 255) / 256, 256>>>(t, sst, p_t6);

    // ---- spatial attention ----
    k_ln_mod<<<NROW, 288>>>(X, p_t6, p_xm, 0, 1);
    k_tgemm<false><<<dim3(3 * CC / TBN, NROW / TBM), 256>>>(p_xm, qkv_s_w, qkv_s_b, p_qkv,
                                                            NROW, 3 * CC, CC);
    k_scores<<<dim3(8, 8, CB * CT * CNH), 256>>>(p_qkv, p_qkv + CC, p_sc, CNH, CS, CS,
                                                 3 * CC, 3 * CC,
                                                 (long)CS * 3 * CC, (long)CS * 3 * CC, scale);
    k_softmax<<<CB * CT * CNH * CS, 128>>>(p_sc, CS, CS, 0);
    k_av<<<dim3(CS / 8, CB * CT * CNH), dim3(72, 8)>>>(p_sc, p_qkv + 2 * CC, p_att, CNH, CS, CS,
                                                       3 * CC, (long)CS * 3 * CC,
                                                       CC, (long)CS * CC);
    k_tgemm<false><<<dim3(CC / TBN, NROW / TBM), 256>>>(p_att, proj_s_w, proj_s_b, p_xm,
                                                        NROW, CC, CC);
    k_resadd<<<NROW, 288>>>(X, p_xm, p_t6, 2);

    // ---- temporal attention (causal) ----
    k_xt_build<<<NROW, 288>>>(X, tpe, p_xm);
    k_tgemm<false><<<dim3(3 * CC / TBN, NROW / TBM), 256>>>(p_xm, qkv_t_w, qkv_t_b, p_qkv,
                                                            NROW, 3 * CC, CC);
    k_scores<<<dim3(1, 1, CB * CS * CNH), 256>>>(p_qkv, p_qkv + CC, p_sc, CNH, CT, CT,
                                                 3 * CC, 3 * CC,
                                                 (long)CT * 3 * CC, (long)CT * 3 * CC, scale);
    k_softmax<<<CB * CS * CNH * CT, 128>>>(p_sc, CT, CT, 1);
    k_av<<<dim3(CT / 8, CB * CS * CNH), dim3(72, 8)>>>(p_sc, p_qkv + 2 * CC, p_att, CNH, CT, CT,
                                                       3 * CC, (long)CT * 3 * CC,
                                                       CC, (long)CT * CC);
    k_tgemm<false><<<dim3(CC / TBN, NROW / TBM), 256>>>(p_att, proj_t_w, proj_t_b, p_xm,
                                                        NROW, CC, CC);
    k_resadd_t<<<NROW, 288>>>(X, p_xm, p_t6, 2);

    // ---- cross attention ----
    k_tgemm<false><<<dim3(CC / TBN, NROW / TBM), 256>>>(X, q_c_w, q_c_b, p_qkv,
                                                        NROW, CC, CC);
    k_tgemm<false><<<dim3(2 * CC / TBN, (CB * CYL + TBM - 1) / TBM), 256>>>(
        y, kv_c_w, kv_c_b, p_kv, CB * CYL, 2 * CC, CC);
    k_scores<<<dim3((CYL + 31) / 32, CN / 32, CB * CNH), 256>>>(p_qkv, p_kv, p_sc, CNH, CN, CYL,
                                                                CC, 2 * CC,
                                                                (long)CN * CC, (long)CYL * 2 * CC,
                                                                scale);
    k_softmax<<<CB * CNH * CN, 128>>>(p_sc, CYL, CN, 0);
    k_av<<<dim3(CN / 8, CB * CNH), dim3(72, 8)>>>(p_sc, p_kv + CC, p_att, CNH, CN, CYL,
                                                  2 * CC, (long)CYL * 2 * CC,
                                                  CC, (long)CN * CC);
    k_tgemm<false><<<dim3(CC / TBN, NROW / TBM), 256>>>(p_att, proj_c_w, proj_c_b, p_xm,
                                                        NROW, CC, CC);
    k_resadd<<<NROW, 288>>>(X, p_xm, p_t6, -1);

    // ---- MLP ----
    k_ln_mod<<<NROW, 288>>>(X, p_t6, p_xm, 3, 4);
    k_tgemm<true><<<dim3(4 * CC / TBN, NROW / TBM), 256>>>(p_xm, fc1_w, fc1_b, p_h,
                                                           NROW, 4 * CC, CC);
    k_tgemm<false><<<dim3(CC / TBN, NROW / TBM), 256>>>(p_h, fc2_w, fc2_b, p_att,
                                                        NROW, CC, 4 * CC);
    k_resadd<<<NROW, 288>>>(X, p_att, p_t6, 5);
}

// round 3
// speedup vs baseline: 3.4109x; 1.3914x over previous
#include <cuda_runtime.h>
#include <math.h>
#include <float.h>
#include <stdint.h>

// ---------------- problem constants ----------------
#define CB   4
#define CT   16
#define CS   256
#define CN   4096
#define CC   1152
#define CNH  16
#define CHD  72
#define CYL  120
#define NROW 16384
#define CC2  (CC * CC)

// ---------------- scratch (device globals) ----------------
__device__ float g_t6[CB * 6 * CC];
__device__ float g_xm[(size_t)NROW * CC];
__device__ float g_qkv[(size_t)NROW * 3 * CC];
__device__ float g_att[(size_t)NROW * CC];
__device__ float g_h[(size_t)NROW * 4 * CC];
__device__ float g_sc[67108864UL];
__device__ float g_kv[CB * CYL * 2 * CC];
__device__ float g_w[20 * CC2];                 // tf32-rounded weights
__device__ float g_yr[CB * CYL * CC];           // tf32-rounded y

// ---------------- helpers ----------------
__device__ __forceinline__ float gelu_tanh(float x) {
    float x3 = x * x * x;
    return 0.5f * x * (1.f + tanhf(0.7978845608028654f * (x + 0.044715f * x3)));
}
__device__ __forceinline__ uint32_t f2tf(float f) {
    uint32_t u;
    asm("cvt.rna.tf32.f32 %0, %1;" : "=r"(u) : "f"(f));
    return u;
}
__device__ __forceinline__ float rndtf(float f) { return __uint_as_float(f2tf(f)); }

__device__ __forceinline__ void cp_async16(void* smem, const void* gmem) {
    uint32_t s = (uint32_t)__cvta_generic_to_shared(smem);
    asm volatile("cp.async.cg.shared.global [%0], [%1], 16;\n" :: "r"(s), "l"(gmem));
}
__device__ __forceinline__ void cp_async16z(void* smem, const void* gmem, int sz) {
    uint32_t s = (uint32_t)__cvta_generic_to_shared(smem);
    asm volatile("cp.async.cg.shared.global [%0], [%1], 16, %2;\n" :: "r"(s), "l"(gmem), "r"(sz));
}
__device__ __forceinline__ void cp_commit() { asm volatile("cp.async.commit_group;\n"); }
template <int Nk>
__device__ __forceinline__ void cp_wait() { asm volatile("cp.async.wait_group %0;\n" :: "n"(Nk)); }

#define MMA_TF32(acc, af, bf)                                                     \
    asm volatile(                                                                 \
        "mma.sync.aligned.m16n8k8.row.col.f32.tf32.tf32.f32 "                     \
        "{%0,%1,%2,%3}, {%4,%5,%6,%7}, {%8,%9}, {%0,%1,%2,%3};\n"                 \
        : "+f"(acc[0]), "+f"(acc[1]), "+f"(acc[2]), "+f"(acc[3])                  \
        : "r"(af[0]), "r"(af[1]), "r"(af[2]), "r"(af[3]), "r"(bf[0]), "r"(bf[1]))

// ---------------- elementwise round ----------------
__global__ void k_round(const float* __restrict__ a, float* __restrict__ o, int n) {
    int i = blockIdx.x * blockDim.x + threadIdx.x;
    if (i < n) o[i] = rndtf(a[i]);
}

// ---------------- modulation ----------------
__global__ void k_mod(const float* __restrict__ t, const float* __restrict__ sst,
                      float* __restrict__ t6) {
    int i = blockIdx.x * blockDim.x + threadIdx.x;
    if (i < CB * 6 * CC) t6[i] = sst[i % (6 * CC)] + t[i];
}

// ---------------- LayerNorm + modulate (tf32-rounded output) ----------------
__global__ void k_ln_mod(const float* __restrict__ X, const float* __restrict__ t6,
                         float* __restrict__ out, int shiftIdx, int scaleIdx) {
    int r = blockIdx.x;
    int b = r >> 12;
    const float* xr = X + (size_t)r * CC;
    const float* sh = t6 + (size_t)(b * 6 + shiftIdx) * CC;
    const float* scl = t6 + (size_t)(b * 6 + scaleIdx) * CC;

    float v[4];
    float s = 0.f, sq = 0.f;
#pragma unroll
    for (int i = 0; i < 4; i++) {
        int c = threadIdx.x + i * 288;
        v[i] = xr[c];
        s += v[i];
        sq += v[i] * v[i];
    }
    __shared__ float s1[9], s2[9], bc[2];
    int lane = threadIdx.x & 31, wid = threadIdx.x >> 5;
#pragma unroll
    for (int off = 16; off > 0; off >>= 1) {
        s += __shfl_xor_sync(0xffffffffu, s, off);
        sq += __shfl_xor_sync(0xffffffffu, sq, off);
    }
    if (lane == 0) { s1[wid] = s; s2[wid] = sq; }
    __syncthreads();
    if (threadIdx.x == 0) {
        float ts = 0.f, tq = 0.f;
        for (int w = 0; w < 9; w++) { ts += s1[w]; tq += s2[w]; }
        float mean = ts * (1.f / CC);
        float var = tq * (1.f / CC) - mean * mean;
        bc[0] = mean;
        bc[1] = rsqrtf(var + 1e-6f);
    }
    __syncthreads();
    float mean = bc[0], rstd = bc[1];
    float* orow = out + (size_t)r * CC;
#pragma unroll
    for (int i = 0; i < 4; i++) {
        int c = threadIdx.x + i * 288;
        orow[c] = rndtf((v[i] - mean) * rstd * (1.f + scl[c]) + sh[c]);
    }
}

// ---------------- TF32 GEMM: C[M,N] = A[M,K] @ W[N,K]^T + bias ----------------
// Inputs are pre-rounded to tf32; no cvt in the hot loop.
#define TBM 128
#define TBN 128
#define TBK 16
#define ASTR 20

// OP: 0 = none, 1 = round output to tf32, 2 = gelu then round
template <int OP>
__global__ __launch_bounds__(256) void k_tgemm(const float* __restrict__ A,
                                               const float* __restrict__ W,
                                               const float* __restrict__ bias,
                                               float* __restrict__ Cmat,
                                               int M, int Nn, int K) {
    __shared__ float As[2][TBM * ASTR];
    __shared__ float Bs[2][TBN * ASTR];

    const int tid = threadIdx.x;
    const int m0 = blockIdx.y * TBM, n0 = blockIdx.x * TBN;
    const int wid = tid >> 5, lane = tid & 31;
    const int wr = wid >> 2, wc = wid & 3;
    const int warp_m = wr * 64, warp_n = wc * 32;
    const int qr = lane >> 2, qc = lane & 3;

    float acc[4][4][4];
#pragma unroll
    for (int mi = 0; mi < 4; mi++)
#pragma unroll
        for (int ni = 0; ni < 4; ni++)
#pragma unroll
            for (int c = 0; c < 4; c++) acc[mi][ni][c] = 0.f;

    auto load_tile = [&](int stg, int kbase) {
#pragma unroll
        for (int i = 0; i < 2; i++) {
            int ch = tid + i * 256;
            int m = ch >> 2;
            int k4 = (ch & 3) * 4;
            int gm = m0 + m; if (gm >= M) gm = M - 1;
            cp_async16(&As[stg][m * ASTR + k4], A + (size_t)gm * K + kbase + k4);
            cp_async16(&Bs[stg][m * ASTR + k4], W + (size_t)(n0 + m) * K + kbase + k4);
        }
    };

    const int KT = K >> 4;
    load_tile(0, 0);
    cp_commit();

    for (int kt = 0; kt < KT; ++kt) {
        int cur = kt & 1;
        if (kt + 1 < KT) {
            load_tile(1 - cur, (kt + 1) << 4);
            cp_commit();
            cp_wait<1>();
        } else {
            cp_wait<0>();
        }
        __syncthreads();

#pragma unroll
        for (int kk = 0; kk < TBK; kk += 8) {
            uint32_t af[4][4], bf[4][2];
#pragma unroll
            for (int mi = 0; mi < 4; mi++) {
                const float* base = &As[cur][(warp_m + mi * 16 + qr) * ASTR + kk + qc];
                af[mi][0] = __float_as_uint(base[0]);
                af[mi][1] = __float_as_uint(base[8 * ASTR]);
                af[mi][2] = __float_as_uint(base[4]);
                af[mi][3] = __float_as_uint(base[8 * ASTR + 4]);
            }
#pragma unroll
            for (int ni = 0; ni < 4; ni++) {
                const float* base = &Bs[cur][(warp_n + ni * 8 + qr) * ASTR + kk + qc];
                bf[ni][0] = __float_as_uint(base[0]);
                bf[ni][1] = __float_as_uint(base[4]);
            }
#pragma unroll
            for (int mi = 0; mi < 4; mi++)
#pragma unroll
                for (int ni = 0; ni < 4; ni++) MMA_TF32(acc[mi][ni], af[mi], bf[ni]);
        }
        __syncthreads();
    }

#pragma unroll
    for (int mi = 0; mi < 4; mi++) {
        int r0 = m0 + warp_m + mi * 16 + qr;
        int r1 = r0 + 8;
#pragma unroll
        for (int ni = 0; ni < 4; ni++) {
            int c0 = n0 + warp_n + ni * 8 + qc * 2;
            float b0 = bias[c0], b1 = bias[c0 + 1];
            float v[4] = {acc[mi][ni][0] + b0, acc[mi][ni][1] + b1,
                          acc[mi][ni][2] + b0, acc[mi][ni][3] + b1};
            if (OP == 2) {
#pragma unroll
                for (int c = 0; c < 4; c++) v[c] = gelu_tanh(v[c]);
            }
            if (OP >= 1) {
#pragma unroll
                for (int c = 0; c < 4; c++) v[c] = rndtf(v[c]);
            }
            if (r0 < M) {
                Cmat[(size_t)r0 * Nn + c0] = v[0];
                Cmat[(size_t)r0 * Nn + c0 + 1] = v[1];
            }
            if (r1 < M) {
                Cmat[(size_t)r1 * Nn + c0] = v[2];
                Cmat[(size_t)r1 * Nn + c0 + 1] = v[3];
            }
        }
    }
}

// ---------------- MMA scores: out[z,i,j] = scale * Q_i . K_j  (d = 72) -------
__global__ __launch_bounds__(256) void k_scores_mma(const float* __restrict__ Q,
                                                    const float* __restrict__ Kd,
                                                    float* __restrict__ out,
                                                    int heads, int Sq, int Sk,
                                                    int qRS, int kRS, long qBS, long kBS,
                                                    float scale) {
    __shared__ float As[2][TBM * ASTR];
    __shared__ float Bs[2][TBN * ASTR];

    const int tid = threadIdx.x;
    int z = blockIdx.z;
    int b = z / heads, h = z - b * heads;
    const float* qb = Q + (long)b * qBS + h * CHD;
    const float* kb = Kd + (long)b * kBS + h * CHD;
    const int i0 = blockIdx.y * TBM, j0 = blockIdx.x * TBN;
    const int wid = tid >> 5, lane = tid & 31;
    const int wr = wid >> 2, wc = wid & 3;
    const int warp_m = wr * 64, warp_n = wc * 32;
    const int qr = lane >> 2, qc = lane & 3;

    float acc[4][4][4];
#pragma unroll
    for (int mi = 0; mi < 4; mi++)
#pragma unroll
        for (int ni = 0; ni < 4; ni++)
#pragma unroll
            for (int c = 0; c < 4; c++) acc[mi][ni][c] = 0.f;

    auto load_tile = [&](int stg, int kbase) {
#pragma unroll
        for (int i = 0; i < 2; i++) {
            int ch = tid + i * 256;
            int m = ch >> 2;
            int k4 = (ch & 3) * 4;
            int sz = (kbase + k4 + 4 <= CHD) ? 16 : 0;
            int gq = i0 + m; if (gq >= Sq) gq = Sq - 1;
            int gk = j0 + m; if (gk >= Sk) gk = Sk - 1;
            cp_async16z(&As[stg][m * ASTR + k4], qb + (long)gq * qRS + kbase + k4, sz);
            cp_async16z(&Bs[stg][m * ASTR + k4], kb + (long)gk * kRS + kbase + k4, sz);
        }
    };

    const int KT = 5;  // 72 -> 5 tiles of 16 (zero-filled tail)
    load_tile(0, 0);
    cp_commit();

    for (int kt = 0; kt < KT; ++kt) {
        int cur = kt & 1;
        if (kt + 1 < KT) {
            load_tile(1 - cur, (kt + 1) << 4);
            cp_commit();
            cp_wait<1>();
        } else {
            cp_wait<0>();
        }
        __syncthreads();

#pragma unroll
        for (int kk = 0; kk < TBK; kk += 8) {
            uint32_t af[4][4], bf[4][2];
#pragma unroll
            for (int mi = 0; mi < 4; mi++) {
                const float* base = &As[cur][(warp_m + mi * 16 + qr) * ASTR + kk + qc];
                af[mi][0] = __float_as_uint(base[0]);
                af[mi][1] = __float_as_uint(base[8 * ASTR]);
                af[mi][2] = __float_as_uint(base[4]);
                af[mi][3] = __float_as_uint(base[8 * ASTR + 4]);
            }
#pragma unroll
            for (int ni = 0; ni < 4; ni++) {
                const float* base = &Bs[cur][(warp_n + ni * 8 + qr) * ASTR + kk + qc];
                bf[ni][0] = __float_as_uint(base[0]);
                bf[ni][1] = __float_as_uint(base[4]);
            }
#pragma unroll
            for (int mi = 0; mi < 4; mi++)
#pragma unroll
                for (int ni = 0; ni < 4; ni++) MMA_TF32(acc[mi][ni], af[mi], bf[ni]);
        }
        __syncthreads();
    }

    float* ob = out + (long)z * Sq * Sk;
#pragma unroll
    for (int mi = 0; mi < 4; mi++) {
        int r0 = i0 + warp_m + mi * 16 + qr;
        int r1 = r0 + 8;
#pragma unroll
        for (int ni = 0; ni < 4; ni++) {
            int c0 = j0 + warp_n + ni * 8 + qc * 2;
            if (c0 < Sk) {
                if (r0 < Sq) ob[(long)r0 * Sk + c0] = acc[mi][ni][0] * scale;
                if (r1 < Sq) ob[(long)r1 * Sk + c0] = acc[mi][ni][2] * scale;
            }
            if (c0 + 1 < Sk) {
                if (r0 < Sq) ob[(long)r0 * Sk + c0 + 1] = acc[mi][ni][1] * scale;
                if (r1 < Sq) ob[(long)r1 * Sk + c0 + 1] = acc[mi][ni][3] * scale;
            }
        }
    }
}

// ---------------- MMA attn@V: O[z,i,d] = sum_j P[z,i,j] V[z,j,d]  (d = 72) ----
#define VSTR 72
__global__ __launch_bounds__(256) void k_av_mma(const float* __restrict__ P,
                                                const float* __restrict__ V,
                                                float* __restrict__ O,
                                                int heads, int Sq, int Sk,
                                                int vRS, long vBS, int oRS, long oBS) {
    __shared__ float As[2][TBM * ASTR];   // P tile: 128 rows x 16 keys
    __shared__ float Bs[2][16 * VSTR];    // V tile: 16 keys x 72

    const int tid = threadIdx.x;
    int z = blockIdx.y;
    int b = z / heads, h = z - b * heads;
    const float* Pb = P + (long)z * Sq * Sk;
    const float* Vb = V + (long)b * vBS + h * CHD;
    float* Ob = O + (long)b * oBS + h * CHD;
    const int i0 = blockIdx.x * TBM;
    const int wid = tid >> 5, lane = tid & 31;
    const int warp_m = wid * 16;
    const int qr = lane >> 2, qc = lane & 3;

    float acc[9][4];
#pragma unroll
    for (int nt = 0; nt < 9; nt++)
#pragma unroll
        for (int c = 0; c < 4; c++) acc[nt][c] = 0.f;

    auto load_tile = [&](int stg, int kb) {
#pragma unroll
        for (int i = 0; i < 2; i++) {
            int ch = tid + i * 256;
            int m = ch >> 2;
            int k4 = (ch & 3) * 4;
            int sz = (kb + k4 + 4 <= Sk) ? 16 : 0;
            int gi = i0 + m; if (gi >= Sq) gi = Sq - 1;
            cp_async16z(&As[stg][m * ASTR + k4], Pb + (long)gi * Sk + kb + k4, sz);
        }
#pragma unroll
        for (int i = 0; i < 2; i++) {
            int ch = tid + i * 256;
            if (ch < 288) {
                int r = ch / 18;
                int c4 = (ch - r * 18) * 4;
                int sz = (kb + r < Sk) ? 16 : 0;
                cp_async16z(&Bs[stg][r * VSTR + c4], Vb + (long)(kb + r) * vRS + c4, sz);
            }
        }
    };

    const int KT = (Sk + 15) >> 4;
    load_tile(0, 0);
    cp_commit();

    for (int kt = 0; kt < KT; ++kt) {
        int cur = kt & 1;
        if (kt + 1 < KT) {
            load_tile(1 - cur, (kt + 1) << 4);
            cp_commit();
            cp_wait<1>();
        } else {
            cp_wait<0>();
        }
        __syncthreads();

#pragma unroll
        for (int kk = 0; kk < 16; kk += 8) {
            uint32_t af[4];
            const float* abase = &As[cur][(warp_m + qr) * ASTR + kk + qc];
            af[0] = __float_as_uint(abase[0]);
            af[1] = __float_as_uint(abase[8 * ASTR]);
            af[2] = __float_as_uint(abase[4]);
            af[3] = __float_as_uint(abase[8 * ASTR + 4]);
#pragma unroll
            for (int nt = 0; nt < 9; nt++) {
                uint32_t bf[2];
                bf[0] = __float_as_uint(Bs[cur][(kk + qc) * VSTR + nt * 8 + qr]);
                bf[1] = __float_as_uint(Bs[cur][(kk + qc + 4) * VSTR + nt * 8 + qr]);
                MMA_TF32(acc[nt], af, bf);
            }
        }
        __syncthreads();
    }

    int r0 = i0 + warp_m + qr;
    int r1 = r0 + 8;
#pragma unroll
    for (int nt = 0; nt < 9; nt++) {
        int c0 = nt * 8 + qc * 2;
        if (r0 < Sq) {
            Ob[(long)r0 * oRS + c0] = rndtf(acc[nt][0]);
            Ob[(long)r0 * oRS + c0 + 1] = rndtf(acc[nt][1]);
        }
        if (r1 < Sq) {
            Ob[(long)r1 * oRS + c0] = rndtf(acc[nt][2]);
            Ob[(long)r1 * oRS + c0 + 1] = rndtf(acc[nt][3]);
        }
    }
}

// ---------------- SIMT scores (temporal only, tiny) ----------------
__global__ void k_scores(const float* __restrict__ Q, const float* __restrict__ Kd,
                         float* __restrict__ out, int heads, int Sq, int Sk,
                         int qRS, int kRS, long qBS, long kBS, float scale) {
    __shared__ float qs[32][73];
    __shared__ float ks[32][73];
    int z = blockIdx.z;
    int b = z / heads, h = z - b * heads;
    const float* qb = Q + (long)b * qBS + h * CHD;
    const float* kb = Kd + (long)b * kBS + h * CHD;
    int i0 = blockIdx.y * 32, j0 = blockIdx.x * 32;
    int tid = threadIdx.x;

    for (int idx = tid; idx < 32 * CHD; idx += 256) {
        int r = idx / CHD, d = idx - r * CHD;
        int i = i0 + r;
        qs[r][d] = (i < Sq) ? qb[(long)i * qRS + d] : 0.f;
        int j = j0 + r;
        ks[r][d] = (j < Sk) ? kb[(long)j * kRS + d] : 0.f;
    }
    __syncthreads();

    int il = tid >> 3;
    int jq = (tid & 7) * 4;
    float acc[4] = {0.f, 0.f, 0.f, 0.f};
#pragma unroll 8
    for (int d = 0; d < CHD; d++) {
        float qv = qs[il][d];
#pragma unroll
        for (int jj = 0; jj < 4; jj++) acc[jj] = fmaf(qv, ks[jq + jj][d], acc[jj]);
    }
    int i = i0 + il;
    if (i < Sq) {
        float* orow = out + (long)z * Sq * Sk + (long)i * Sk;
#pragma unroll
        for (int jj = 0; jj < 4; jj++) {
            int j = j0 + jq + jj;
            if (j < Sk) orow[j] = acc[jj] * scale;
        }
    }
}

// ---------------- softmax (tf32-rounded output) ----------------
__global__ void k_softmax(float* __restrict__ sc, int L, int Sq, int causal) {
    long row = blockIdx.x;
    float* p = sc + row * (long)L;
    int i = (int)(row % Sq);
    int tid = threadIdx.x;
    int j0 = tid, j1 = tid + 128;

    float a0 = -FLT_MAX, a1 = -FLT_MAX;
    if (j0 < L) { a0 = p[j0]; if (causal && j0 > i) a0 = -FLT_MAX; }
    if (j1 < L) { a1 = p[j1]; if (causal && j1 > i) a1 = -FLT_MAX; }

    __shared__ float red[4];
    float m = fmaxf(a0, a1);
#pragma unroll
    for (int off = 16; off > 0; off >>= 1) m = fmaxf(m, __shfl_xor_sync(0xffffffffu, m, off));
    if ((tid & 31) == 0) red[tid >> 5] = m;
    __syncthreads();
    m = fmaxf(fmaxf(red[0], red[1]), fmaxf(red[2], red[3]));
    __syncthreads();

    float e0 = (j0 < L) ? expf(a0 - m) : 0.f;
    float e1 = (j1 < L) ? expf(a1 - m) : 0.f;
    float s = e0 + e1;
#pragma unroll
    for (int off = 16; off > 0; off >>= 1) s += __shfl_xor_sync(0xffffffffu, s, off);
    if ((tid & 31) == 0) red[tid >> 5] = s;
    __syncthreads();
    s = red[0] + red[1] + red[2] + red[3];
    float inv = 1.f / s;
    if (j0 < L) p[j0] = rndtf(e0 * inv);
    if (j1 < L) p[j1] = rndtf(e1 * inv);
}

// ---------------- SIMT attn@V (temporal only; rounded output) ----------------
__global__ void k_av(const float* __restrict__ Asc, const float* __restrict__ V,
                     float* __restrict__ O, int heads, int Sq, int Sk,
                     int vRS, long vBS, int oRS, long oBS) {
    __shared__ float vs[32][73];
    __shared__ float as[8][32];
    int z = blockIdx.y;
    int b = z / heads, h = z - b * heads;
    const float* Ab = Asc + (long)z * Sq * Sk;
    const float* Vb = V + (long)b * vBS + h * CHD;
    float* Ob = O + (long)b * oBS + h * CHD;

    int d = threadIdx.x, ii = threadIdx.y;
    int i = blockIdx.x * 8 + ii;
    int tid = ii * 72 + d;
    float acc = 0.f;

    for (int jt = 0; jt < Sk; jt += 32) {
        for (int idx = tid; idx < 32 * CHD; idx += 576) {
            int r = idx / CHD, dd = idx - r * CHD;
            int j = jt + r;
            vs[r][dd] = (j < Sk) ? Vb[(long)j * vRS + dd] : 0.f;
        }
        if (tid < 256) {
            int r = tid >> 5, jj = tid & 31;
            int ig = blockIdx.x * 8 + r;
            int j = jt + jj;
            as[r][jj] = (ig < Sq && j < Sk) ? Ab[(long)ig * Sk + j] : 0.f;
        }
        __syncthreads();
#pragma unroll
        for (int jj = 0; jj < 32; jj++) acc = fmaf(as[ii][jj], vs[jj][d], acc);
        __syncthreads();
    }
    if (i < Sq) Ob[(long)i * oRS + d] = rndtf(acc);
}

// ---------------- build temporal input (rounded) ----------------
__global__ void k_xt_build(const float* __restrict__ X, const float* __restrict__ tpe,
                           float* __restrict__ out) {
    int r = blockIdx.x;
    int t = r & 15;
    int bs = r >> 4;
    int s = bs & 255;
    int b = bs >> 8;
    const float* xr = X + ((size_t)b * CN + t * CS + s) * CC;
    const float* tp = tpe + (size_t)t * CC;
    float* orow = out + (size_t)r * CC;
#pragma unroll
    for (int i = 0; i < 4; i++) {
        int c = threadIdx.x + i * 288;
        orow[c] = rndtf(xr[c] + tp[c]);
    }
}

// ---------------- residual add ----------------
__global__ void k_resadd(float* __restrict__ X, const float* __restrict__ src,
                         const float* __restrict__ t6, int gi) {
    int r = blockIdx.x;
    int b = r >> 12;
    float* xr = X + (size_t)r * CC;
    const float* sr = src + (size_t)r * CC;
    const float* gr = (gi >= 0) ? t6 + (size_t)(b * 6 + gi) * CC : nullptr;
#pragma unroll
    for (int i = 0; i < 4; i++) {
        int c = threadIdx.x + i * 288;
        float g = gr ? gr[c] : 1.f;
        xr[c] += g * sr[c];
    }
}

// ---------------- temporal residual scatter + rounded copy of X ----------------
__global__ void k_resadd_t(float* __restrict__ X, const float* __restrict__ src,
                           const float* __restrict__ t6, int gi,
                           float* __restrict__ xr_out) {
    int r = blockIdx.x;
    int b = r >> 12;
    int n = r & 4095;
    int t = n >> 8;
    int s = n & 255;
    long srow = ((long)(b * CS + s) * CT + t) * CC;
    float* xr = X + (size_t)r * CC;
    const float* sr = src + srow;
    const float* gr = t6 + (size_t)(b * 6 + gi) * CC;
    float* orow = xr_out + (size_t)r * CC;
#pragma unroll
    for (int i = 0; i < 4; i++) {
        int c = threadIdx.x + i * 288;
        float v = xr[c] + gr[c] * sr[c];
        xr[c] = v;
        orow[c] = rndtf(v);
    }
}

// =======================================================================
extern "C" void kernel_launch(void* const* d_in, const int* in_sizes, int n_in,
                              void* d_out, int out_size) {
    const float* x      = (const float*)d_in[0];
    const float* y      = (const float*)d_in[1];
    const float* t      = (const float*)d_in[2];
    const float* tpe    = (const float*)d_in[3];
    const float* sst    = (const float*)d_in[4];
    const float* qkv_s_w = (const float*)d_in[5];
    const float* qkv_s_b = (const float*)d_in[6];
    const float* proj_s_w = (const float*)d_in[7];
    const float* proj_s_b = (const float*)d_in[8];
    const float* qkv_t_w = (const float*)d_in[9];
    const float* qkv_t_b = (const float*)d_in[10];
    const float* proj_t_w = (const float*)d_in[11];
    const float* proj_t_b = (const float*)d_in[12];
    const float* q_c_w  = (const float*)d_in[13];
    const float* q_c_b  = (const float*)d_in[14];
    const float* kv_c_w = (const float*)d_in[15];
    const float* kv_c_b = (const float*)d_in[16];
    const float* proj_c_w = (const float*)d_in[17];
    const float* proj_c_b = (const float*)d_in[18];
    const float* fc1_w  = (const float*)d_in[19];
    const float* fc1_b  = (const float*)d_in[20];
    const float* fc2_w  = (const float*)d_in[21];
    const float* fc2_b  = (const float*)d_in[22];
    float* X = (float*)d_out;

    float *p_t6, *p_xm, *p_qkv, *p_att, *p_h, *p_sc, *p_kv, *p_w, *p_yr;
    cudaGetSymbolAddress((void**)&p_t6, g_t6);
    cudaGetSymbolAddress((void**)&p_xm, g_xm);
    cudaGetSymbolAddress((void**)&p_qkv, g_qkv);
    cudaGetSymbolAddress((void**)&p_att, g_att);
    cudaGetSymbolAddress((void**)&p_h, g_h);
    cudaGetSymbolAddress((void**)&p_sc, g_sc);
    cudaGetSymbolAddress((void**)&p_kv, g_kv);
    cudaGetSymbolAddress((void**)&p_w, g_w);
    cudaGetSymbolAddress((void**)&p_yr, g_yr);

    const float scale = 0.11785113019775793f;  // 1/sqrt(72)

    // rounded weight copies (offsets in units of CC2)
    float* w_qkv_s = p_w + (size_t)0 * CC2;
    float* w_proj_s = p_w + (size_t)3 * CC2;
    float* w_qkv_t = p_w + (size_t)4 * CC2;
    float* w_proj_t = p_w + (size_t)7 * CC2;
    float* w_q_c   = p_w + (size_t)8 * CC2;
    float* w_kv_c  = p_w + (size_t)9 * CC2;
    float* w_proj_c = p_w + (size_t)11 * CC2;
    float* w_fc1   = p_w + (size_t)12 * CC2;
    float* w_fc2   = p_w + (size_t)16 * CC2;

    auto rnd = [&](const float* src, float* dst, size_t n) {
        k_round<<<(int)((n + 255) / 256), 256>>>(src, dst, (int)n);
    };
    rnd(qkv_s_w, w_qkv_s, (size_t)3 * CC2);
    rnd(proj_s_w, w_proj_s, CC2);
    rnd(qkv_t_w, w_qkv_t, (size_t)3 * CC2);
    rnd(proj_t_w, w_proj_t, CC2);
    rnd(q_c_w, w_q_c, CC2);
    rnd(kv_c_w, w_kv_c, (size_t)2 * CC2);
    rnd(proj_c_w, w_proj_c, CC2);
    rnd(fc1_w, w_fc1, (size_t)4 * CC2);
    rnd(fc2_w, w_fc2, (size_t)4 * CC2);
    rnd(y, p_yr, (size_t)CB * CYL * CC);

    cudaMemcpyAsync(X, x, (size_t)NROW * CC * sizeof(float), cudaMemcpyDeviceToDevice);
    k_mod<<<(CB * 6 * CC + 255) / 256, 256>>>(t, sst, p_t6);

    // ---- spatial attention ----
    k_ln_mod<<<NROW, 288>>>(X, p_t6, p_xm, 0, 1);
    k_tgemm<1><<<dim3(3 * CC / TBN, NROW / TBM), 256>>>(p_xm, w_qkv_s, qkv_s_b, p_qkv,
                                                        NROW, 3 * CC, CC);
    k_scores_mma<<<dim3(2, 2, CB * CT * CNH), 256>>>(p_qkv, p_qkv + CC, p_sc, CNH, CS, CS,
                                                     3 * CC, 3 * CC,
                                                     (long)CS * 3 * CC, (long)CS * 3 * CC, scale);
    k_softmax<<<CB * CT * CNH * CS, 128>>>(p_sc, CS, CS, 0);
    k_av_mma<<<dim3(2, CB * CT * CNH), 256>>>(p_sc, p_qkv + 2 * CC, p_att, CNH, CS, CS,
                                              3 * CC, (long)CS * 3 * CC, CC, (long)CS * CC);
    k_tgemm<0><<<dim3(CC / TBN, NROW / TBM), 256>>>(p_att, w_proj_s, proj_s_b, p_xm,
                                                    NROW, CC, CC);
    k_resadd<<<NROW, 288>>>(X, p_xm, p_t6, 2);

    // ---- temporal attention (causal, tiny seq = SIMT path) ----
    k_xt_build<<<NROW, 288>>>(X, tpe, p_xm);
    k_tgemm<1><<<dim3(3 * CC / TBN, NROW / TBM), 256>>>(p_xm, w_qkv_t, qkv_t_b, p_qkv,
                                                        NROW, 3 * CC, CC);
    k_scores<<<dim3(1, 1, CB * CS * CNH), 256>>>(p_qkv, p_qkv + CC, p_sc, CNH, CT, CT,
                                                 3 * CC, 3 * CC,
                                                 (long)CT * 3 * CC, (long)CT * 3 * CC, scale);
    k_softmax<<<CB * CS * CNH * CT, 128>>>(p_sc, CT, CT, 1);
    k_av<<<dim3(CT / 8, CB * CS * CNH), dim3(72, 8)>>>(p_sc, p_qkv + 2 * CC, p_att, CNH, CT, CT,
                                                       3 * CC, (long)CT * 3 * CC,
                                                       CC, (long)CT * CC);
    k_tgemm<0><<<dim3(CC / TBN, NROW / TBM), 256>>>(p_att, w_proj_t, proj_t_b, p_xm,
                                                    NROW, CC, CC);
    k_resadd_t<<<NROW, 288>>>(X, p_xm, p_t6, 2, p_h);  // p_h = rounded X copy

    // ---- cross attention ----
    k_tgemm<1><<<dim3(CC / TBN, NROW / TBM), 256>>>(p_h, w_q_c, q_c_b, p_qkv,
                                                    NROW, CC, CC);
    k_tgemm<1><<<dim3(2 * CC / TBN, (CB * CYL + TBM - 1) / TBM), 256>>>(
        p_yr, w_kv_c, kv_c_b, p_kv, CB * CYL, 2 * CC, CC);
    k_scores_mma<<<dim3(1, CN / TBM, CB * CNH), 256>>>(p_qkv, p_kv, p_sc, CNH, CN, CYL,
                                                       CC, 2 * CC,
                                                       (long)CN * CC, (long)CYL * 2 * CC, scale);
    k_softmax<<<CB * CNH * CN, 128>>>(p_sc, CYL, CN, 0);
    k_av_mma<<<dim3(CN / TBM, CB * CNH), 256>>>(p_sc, p_kv + CC, p_att, CNH, CN, CYL,
                                                2 * CC, (long)CYL * 2 * CC, CC, (long)CN * CC);
    k_tgemm<0><<<dim3(CC / TBN, NROW / TBM), 256>>>(p_att, w_proj_c, proj_c_b, p_xm,
                                                    NROW, CC, CC);
    k_resadd<<<NROW, 288>>>(X, p_xm, p_t6, -1);

    // ---- MLP ----
    k_ln_mod<<<NROW, 288>>>(X, p_t6, p_xm, 3, 4);
    k_tgemm<2><<<dim3(4 * CC / TBN, NROW / TBM), 256>>>(p_xm, w_fc1, fc1_b, p_h,
                                                        NROW, 4 * CC, CC);
    k_tgemm<0><<<dim3(CC / TBN, NROW / TBM), 256>>>(p_h, w_fc2, fc2_b, p_att,
                                                    NROW, CC, 4 * CC);
    k_resadd<<<NROW, 288>>>(X, p_att, p_t6, 5);
}